// round 11
// baseline (speedup 1.0000x reference)
#include <cuda_runtime.h>
#include <cuda_fp16.h>
#include <cuda_bf16.h>
#include <math.h>

#define NT_   32768
#define B_    16
#define N_    2048
#define INCH_ 128
#define H_    4
#define C_    64
#define HC_   256
#define E_    524288
#define FC0_  1024
#define FC1_  512
#define OMIC_ 128
#define OUT_  2

// ---------------- scratch (static device globals) --------------------------
__device__ __align__(16) float g_xw[NT_ * HC_];
__device__ __align__(16) __half g_xwh[NT_ * HC_];
__device__ __align__(16) float g_h [NT_ * HC_];
__device__ __align__(16) float g_asrc[NT_ * 4];
__device__ __align__(16) float g_adst[NT_ * 4];
__device__ int   g_deg[NT_];
__device__ int   g_cur[NT_];
__device__ int   g_row[NT_ + 1];
__device__ int   g_blk[128];
__device__ int   g_csr[E_];
__device__ __align__(16) float g_feat[B_ * 3 * N_];
__device__ __align__(16) float g_part[12 * B_ * FC0_];
__device__ __align__(16) float g_e0[B_ * FC0_];
__device__ __align__(16) float g_e1[B_ * FC1_];
__device__ int   g_i64;

__device__ __forceinline__ float elu1(float x)  { return x > 0.f ? x : (expf(x) - 1.f); }
__device__ __forceinline__ float lrelu(float x) { return x > 0.f ? x : 0.2f * x; }

__device__ __forceinline__ int ld_idx(const void* ei, int i) {
    if (g_i64) return (int)((const long long*)ei)[i];
    return ((const int*)ei)[i];
}

// ---------------- zero + dtype detect ----------------------------------------
__global__ void k_zero(const void* ei) {
    int i = blockIdx.x * blockDim.x + threadIdx.x;
    if (i < NT_) { g_deg[i] = 0; g_cur[i] = 0; }
    if (blockIdx.x == 0 && threadIdx.x < 32) {
        const long long* p64 = (const long long*)ei;
        long long v = p64[threadIdx.x];
        unsigned bad = __ballot_sync(0xffffffffu, v < 0 || v >= NT_);
        if (threadIdx.x == 0) g_i64 = (bad == 0);
    }
}

__global__ void k_deg(const void* __restrict__ ei) {
    int e = blockIdx.x * blockDim.x + threadIdx.x;
    if (e < E_) atomicAdd(&g_deg[ld_idx(ei, E_ + e) & (NT_ - 1)], 1);
}

__global__ void k_scan1() {
    __shared__ int wt[8];
    int t = threadIdx.x;
    int i = blockIdx.x * 256 + t;
    int v = g_deg[i];
    int lane = t & 31, w = t >> 5;
    int inc = v;
#pragma unroll
    for (int off = 1; off < 32; off <<= 1) {
        int u = __shfl_up_sync(0xffffffffu, inc, off);
        if (lane >= off) inc += u;
    }
    if (lane == 31) wt[w] = inc;
    __syncthreads();
    if (t == 0) {
        int run = 0;
#pragma unroll
        for (int k = 0; k < 8; k++) { int x = wt[k]; wt[k] = run; run += x; }
        g_blk[blockIdx.x] = run;
    }
    __syncthreads();
    g_row[i] = inc - v + wt[w];
}

__global__ void k_scan3b() {
    __shared__ int part[4];
    int t = threadIdx.x;
    int v = (t < 128 && t < blockIdx.x) ? g_blk[t] : 0;
    if (t < 128) {
        int u = v;
#pragma unroll
        for (int off = 16; off >= 1; off >>= 1)
            u += __shfl_xor_sync(0xffffffffu, u, off);
        if ((t & 31) == 0) part[t >> 5] = u;
    }
    __syncthreads();
    int pre = part[0] + part[1] + part[2] + part[3];
    g_row[blockIdx.x * 256 + t] += pre;
    if (blockIdx.x == 127 && t == 255) g_row[NT_] = pre + g_blk[127];
}

__global__ void k_scatter(const void* __restrict__ ei) {
    int e = blockIdx.x * blockDim.x + threadIdx.x;
    if (e < E_) {
        int d = ld_idx(ei, E_ + e) & (NT_ - 1);
        int s = ld_idx(ei, e) & (NT_ - 1);
        int pos = g_row[d] + atomicAdd(&g_cur[d], 1);
        g_csr[pos] = s;
    }
}

__global__ void k_sortseg() {
    int n = blockIdx.x * blockDim.x + threadIdx.x;
    if (n >= NT_) return;
    int r0 = g_row[n], r1 = g_row[n + 1];
    int len = r1 - r0;
    if (len <= 1) return;
    if (len <= 96) {
        int buf[96];
        for (int i = 0; i < len; i++) buf[i] = g_csr[r0 + i];
        for (int i = 1; i < len; i++) {
            int v = buf[i]; int j = i - 1;
            while (j >= 0 && buf[j] > v) { buf[j + 1] = buf[j]; j--; }
            buf[j + 1] = v;
        }
        for (int i = 0; i < len; i++) g_csr[r0 + i] = buf[i];
    } else {
        for (int i = r0 + 1; i < r1; i++) {
            int v = g_csr[i]; int j = i - 1;
            while (j >= r0 && g_csr[j] > v) { g_csr[j + 1] = g_csr[j]; j--; }
            g_csr[j + 1] = v;
        }
    }
}

// ---------------- bf16 3-pass tensor GEMM + fused attention dots -------------
__device__ __forceinline__ void mma16(float* c, const unsigned* a,
                                      unsigned b0, unsigned b1) {
    asm volatile(
        "mma.sync.aligned.m16n8k16.row.col.f32.bf16.bf16.f32 "
        "{%0,%1,%2,%3},{%4,%5,%6,%7},{%8,%9},{%0,%1,%2,%3};"
        : "+f"(c[0]), "+f"(c[1]), "+f"(c[2]), "+f"(c[3])
        : "r"(a[0]), "r"(a[1]), "r"(a[2]), "r"(a[3]), "r"(b0), "r"(b1));
}

__device__ __forceinline__ unsigned sptr(const void* p) {
    return (unsigned)__cvta_generic_to_shared(p);
}

__device__ __forceinline__ void ldsm4(unsigned* r, unsigned addr) {
    asm volatile("ldmatrix.sync.aligned.m8n8.x4.shared.b16 {%0,%1,%2,%3}, [%4];"
                 : "=r"(r[0]), "=r"(r[1]), "=r"(r[2]), "=r"(r[3]) : "r"(addr));
}

__device__ __forceinline__ void ldsm4t(unsigned* r, unsigned addr) {
    asm volatile("ldmatrix.sync.aligned.m8n8.x4.trans.shared.b16 {%0,%1,%2,%3}, [%4];"
                 : "=r"(r[0]), "=r"(r[1]), "=r"(r[2]), "=r"(r[3]) : "r"(addr));
}

__global__ __launch_bounds__(256, 2)
void k_gemm_tc(const float* __restrict__ Aext, int useH,
               const float* __restrict__ W, int K,
               const float* __restrict__ att_s, const float* __restrict__ att_d) {
    const float* A = useH ? (const float*)g_h : Aext;
    __shared__ __nv_bfloat16 AsH[128][40];
    __shared__ __nv_bfloat16 AsL[128][40];
    __shared__ __nv_bfloat16 BsH[32][136];
    __shared__ __nv_bfloat16 BsL[32][136];
    int tid = threadIdx.x;
    int lid = tid & 31, wid = tid >> 5;
    int wr = wid >> 1, wc = wid & 1;
    int lrow = lid & 7, seg = lid >> 3;

    const float* Ab = A + (size_t)blockIdx.x * 128 * K;
    const float* Wb = W + blockIdx.y * 128;

    float c[2][8][4];
#pragma unroll
    for (int mt = 0; mt < 2; mt++)
#pragma unroll
        for (int nt = 0; nt < 8; nt++)
#pragma unroll
            for (int q = 0; q < 4; q++) c[mt][nt][q] = 0.f;

    for (int k0 = 0; k0 < K; k0 += 32) {
#pragma unroll
        for (int i = 0; i < 4; i++) {
            int id = tid + 256 * i;
            int row = id >> 3, kq = id & 7;
            float4 v = *(const float4*)(Ab + (size_t)row * K + k0 + kq * 4);
            __nv_bfloat162 h01 = __floats2bfloat162_rn(v.x, v.y);
            __nv_bfloat162 h23 = __floats2bfloat162_rn(v.z, v.w);
            __nv_bfloat162 l01 = __floats2bfloat162_rn(v.x - __bfloat162float(h01.x),
                                                       v.y - __bfloat162float(h01.y));
            __nv_bfloat162 l23 = __floats2bfloat162_rn(v.z - __bfloat162float(h23.x),
                                                       v.w - __bfloat162float(h23.y));
            *(__nv_bfloat162*)&AsH[row][kq * 4]     = h01;
            *(__nv_bfloat162*)&AsH[row][kq * 4 + 2] = h23;
            *(__nv_bfloat162*)&AsL[row][kq * 4]     = l01;
            *(__nv_bfloat162*)&AsL[row][kq * 4 + 2] = l23;
        }
#pragma unroll
        for (int i = 0; i < 4; i++) {
            int id = tid + 256 * i;
            int kr = id >> 5, nq = id & 31;
            float4 v = *(const float4*)(Wb + (size_t)(k0 + kr) * HC_ + nq * 4);
            __nv_bfloat162 h01 = __floats2bfloat162_rn(v.x, v.y);
            __nv_bfloat162 h23 = __floats2bfloat162_rn(v.z, v.w);
            __nv_bfloat162 l01 = __floats2bfloat162_rn(v.x - __bfloat162float(h01.x),
                                                       v.y - __bfloat162float(h01.y));
            __nv_bfloat162 l23 = __floats2bfloat162_rn(v.z - __bfloat162float(h23.x),
                                                       v.w - __bfloat162float(h23.y));
            *(__nv_bfloat162*)&BsH[kr][nq * 4]     = h01;
            *(__nv_bfloat162*)&BsH[kr][nq * 4 + 2] = h23;
            *(__nv_bfloat162*)&BsL[kr][nq * 4]     = l01;
            *(__nv_bfloat162*)&BsL[kr][nq * 4 + 2] = l23;
        }
        __syncthreads();

#pragma unroll
        for (int ks = 0; ks < 2; ks++) {
            int kc = ks * 16;
            unsigned aH[2][4], aL[2][4];
            int ar = (seg & 1) * 8 + lrow;
            int ac = kc + (seg >> 1) * 8;
#pragma unroll
            for (int mt = 0; mt < 2; mt++) {
                int m = wr * 32 + mt * 16 + ar;
                ldsm4(aH[mt], sptr(&AsH[m][ac]));
                ldsm4(aL[mt], sptr(&AsL[m][ac]));
            }
            int br = kc + (seg & 1) * 8 + lrow;
            int bcoff = (seg >> 1) * 8;
#pragma unroll
            for (int ntp = 0; ntp < 4; ntp++) {
                int n0 = wc * 64 + ntp * 16 + bcoff;
                unsigned bH[4], bL[4];
                ldsm4t(bH, sptr(&BsH[br][n0]));
                ldsm4t(bL, sptr(&BsL[br][n0]));
#pragma unroll
                for (int half = 0; half < 2; half++) {
                    int nt = 2 * ntp + half;
                    unsigned b0H = bH[2 * half], b1H = bH[2 * half + 1];
                    unsigned b0L = bL[2 * half], b1L = bL[2 * half + 1];
#pragma unroll
                    for (int mt = 0; mt < 2; mt++) {
                        mma16(c[mt][nt], aH[mt], b0H, b1H);
                        mma16(c[mt][nt], aL[mt], b0H, b1H);
                        mma16(c[mt][nt], aH[mt], b0L, b1L);
                    }
                }
            }
        }
        __syncthreads();
    }

    int g4 = lid >> 2, t4 = lid & 3;

    // ---- store xw (fp32 + fp16 copy)
#pragma unroll
    for (int mt = 0; mt < 2; mt++) {
#pragma unroll
        for (int nt = 0; nt < 8; nt++) {
            int row = blockIdx.x * 128 + wr * 32 + mt * 16 + g4;
            int col = blockIdx.y * 128 + wc * 64 + nt * 8 + 2 * t4;
            float2 v0 = {c[mt][nt][0], c[mt][nt][1]};
            float2 v1 = {c[mt][nt][2], c[mt][nt][3]};
            *(float2*)(g_xw + (size_t)row * HC_ + col)       = v0;
            *(float2*)(g_xw + (size_t)(row + 8) * HC_ + col) = v1;
            *(__half2*)(g_xwh + (size_t)row * HC_ + col)       = __floats2half2_rn(v0.x, v0.y);
            *(__half2*)(g_xwh + (size_t)(row + 8) * HC_ + col) = __floats2half2_rn(v1.x, v1.y);
        }
    }

    // ---- fused attention dots: this warp's 64 cols == one head
    int head = blockIdx.y * 2 + wc;
    const float* Asv = att_s + head * 64;
    const float* Adv = att_d + head * 64;
#pragma unroll
    for (int mt = 0; mt < 2; mt++) {
        float s0 = 0.f, s1 = 0.f, d0 = 0.f, d1 = 0.f;
#pragma unroll
        for (int nt = 0; nt < 8; nt++) {
            int cb = nt * 8 + 2 * t4;
            float a0 = Asv[cb], a1 = Asv[cb + 1];
            float b0 = Adv[cb], b1 = Adv[cb + 1];
            s0 += c[mt][nt][0] * a0 + c[mt][nt][1] * a1;
            s1 += c[mt][nt][2] * a0 + c[mt][nt][3] * a1;
            d0 += c[mt][nt][0] * b0 + c[mt][nt][1] * b1;
            d1 += c[mt][nt][2] * b0 + c[mt][nt][3] * b1;
        }
#pragma unroll
        for (int off = 1; off <= 2; off <<= 1) {
            s0 += __shfl_xor_sync(0xffffffffu, s0, off);
            s1 += __shfl_xor_sync(0xffffffffu, s1, off);
            d0 += __shfl_xor_sync(0xffffffffu, d0, off);
            d1 += __shfl_xor_sync(0xffffffffu, d1, off);
        }
        if (t4 == 0) {
            int r = blockIdx.x * 128 + wr * 32 + mt * 16 + g4;
            g_asrc[r * 4 + head]       = s0;
            g_adst[r * 4 + head]       = d0;
            g_asrc[(r + 8) * 4 + head] = s1;
            g_adst[(r + 8) * 4 + head] = d1;
        }
    }
}

// ---------------- GAT aggregation (warp per node, fp16 gather, prefetch) ------
__global__ void k_agg(const float* __restrict__ bias,
                      const float* __restrict__ poolw,
                      const float* __restrict__ poolb,
                      int writeH, int seg) {
    int n = (blockIdx.x * blockDim.x + threadIdx.x) >> 5;
    int lane = threadIdx.x & 31;
    if (n >= NT_) return;
    int h = lane >> 3;

    float4 d4 = *(const float4*)(g_adst + n * 4);
    float4 s4 = *(const float4*)(g_asrc + n * 4);
    float adh = (h == 0) ? d4.x : (h == 1) ? d4.y : (h == 2) ? d4.z : d4.w;
    float ash = (h == 0) ? s4.x : (h == 1) ? s4.y : (h == 2) ? s4.z : s4.w;

    int r0 = g_row[n], r1 = g_row[n + 1];

    float wself = __expf(lrelu(ash + adh));
    float den = wself;
    const float4* xp = (const float4*)(g_xw + (size_t)n * HC_ + lane * 8);
    float4 q0 = xp[0], q1 = xp[1];
    float4 acc0 = {wself*q0.x, wself*q0.y, wself*q0.z, wself*q0.w};
    float4 acc1 = {wself*q1.x, wself*q1.y, wself*q1.z, wself*q1.w};

    // software-pipelined index/alpha chain
    int sN = 0; float asN = 0.f;
    if (r0 < r1) { sN = g_csr[r0]; asN = g_asrc[sN * 4 + h]; }
    for (int e = r0; e < r1; e++) {
        int s = sN; float as = asN;
        int eN = (e + 1 < r1) ? e + 1 : e;
        sN = g_csr[eN];
        asN = g_asrc[sN * 4 + h];
        float wgt = __expf(lrelu(as + adh));
        den += wgt;
        uint4 q = *(const uint4*)(g_xwh + (size_t)s * HC_ + lane * 8);
        float2 f0 = __half22float2(*(__half2*)&q.x);
        float2 f1 = __half22float2(*(__half2*)&q.y);
        float2 f2 = __half22float2(*(__half2*)&q.z);
        float2 f3 = __half22float2(*(__half2*)&q.w);
        acc0.x += wgt * f0.x; acc0.y += wgt * f0.y;
        acc0.z += wgt * f1.x; acc0.w += wgt * f1.y;
        acc1.x += wgt * f2.x; acc1.y += wgt * f2.y;
        acc1.z += wgt * f3.x; acc1.w += wgt * f3.y;
    }
    float rden = 1.f / (den + 1e-16f);
    acc0.x *= rden; acc0.y *= rden; acc0.z *= rden; acc0.w *= rden;
    acc1.x *= rden; acc1.y *= rden; acc1.z *= rden; acc1.w *= rden;

    const float* bp = bias + lane * 8;
    float v[8];
    v[0] = elu1(acc0.x + bp[0]); v[1] = elu1(acc0.y + bp[1]);
    v[2] = elu1(acc0.z + bp[2]); v[3] = elu1(acc0.w + bp[3]);
    v[4] = elu1(acc1.x + bp[4]); v[5] = elu1(acc1.y + bp[5]);
    v[6] = elu1(acc1.z + bp[6]); v[7] = elu1(acc1.w + bp[7]);

    if (writeH) {
        float4 o0 = {v[0], v[1], v[2], v[3]};
        float4 o1 = {v[4], v[5], v[6], v[7]};
        *(float4*)(g_h + (size_t)n * HC_ + lane * 8)     = o0;
        *(float4*)(g_h + (size_t)n * HC_ + lane * 8 + 4) = o1;
    }

    const float* pw = poolw + lane * 8;
    float p = v[0]*pw[0] + v[1]*pw[1] + v[2]*pw[2] + v[3]*pw[3]
            + v[4]*pw[4] + v[5]*pw[5] + v[6]*pw[6] + v[7]*pw[7];
#pragma unroll
    for (int off = 16; off >= 1; off >>= 1)
        p += __shfl_xor_sync(0xffffffffu, p, off);
    if (lane == 0)
        g_feat[(n >> 11) * (3 * N_) + seg * N_ + (n & 2047)] = p + poolb[0];
}

// ---------------- x0: per-node mean ------------------------------------------
__global__ void k_x0(const float* __restrict__ x) {
    int n = (blockIdx.x * blockDim.x + threadIdx.x) >> 5;
    int lane = threadIdx.x & 31;
    if (n >= NT_) return;
    float4 v = *(const float4*)(x + (size_t)n * INCH_ + lane * 4);
    float s = v.x + v.y + v.z + v.w;
#pragma unroll
    for (int off = 16; off >= 1; off >>= 1)
        s += __shfl_xor_sync(0xffffffffu, s, off);
    if (lane == 0)
        g_feat[(n >> 11) * (3 * N_) + (n & 2047)] = s * (1.f / 128.f);
}

// ---------------- LayerNorm in place ------------------------------------------
__global__ void k_ln(const float* __restrict__ w, const float* __restrict__ b,
                     int mode) {
    __shared__ float red[8];
    __shared__ float tot;
    int row = (mode == 0) ? ((blockIdx.x >> 1) * 3 + (blockIdx.x & 1))
                          : (blockIdx.x * 3 + 2);
    float* p = g_feat + (row / 3) * (3 * N_) + (row % 3) * N_;
    int t = threadIdx.x;
    float v[8];
    float s = 0.f;
#pragma unroll
    for (int i = 0; i < 8; i++) { v[i] = p[t + 256 * i]; s += v[i]; }
#pragma unroll
    for (int off = 16; off >= 1; off >>= 1) s += __shfl_xor_sync(0xffffffffu, s, off);
    if ((t & 31) == 0) red[t >> 5] = s;
    __syncthreads();
    if (t == 0) { float z = 0.f; for (int i = 0; i < 8; i++) z += red[i]; tot = z; }
    __syncthreads();
    float mu = tot * (1.f / 2048.f);
    float q = 0.f;
#pragma unroll
    for (int i = 0; i < 8; i++) { float d = v[i] - mu; q += d * d; }
#pragma unroll
    for (int off = 16; off >= 1; off >>= 1) q += __shfl_xor_sync(0xffffffffu, q, off);
    __syncthreads();
    if ((t & 31) == 0) red[t >> 5] = q;
    __syncthreads();
    if (t == 0) { float z = 0.f; for (int i = 0; i < 8; i++) z += red[i]; tot = z; }
    __syncthreads();
    float r = rsqrtf(tot * (1.f / 2048.f) + 1e-5f);
#pragma unroll
    for (int i = 0; i < 8; i++) {
        int idx = t + 256 * i;
        p[idx] = (v[i] - mu) * r * w[idx] + b[idx];
    }
}

// ---------------- FC partial GEMM ---------------------------------------------
__global__ void k_fc(int which, const float* __restrict__ W, int K, int Ncol,
                     int kbase, int part_base, int kslab) {
    const float* A = (which == 0) ? (const float*)g_feat
                   : (which == 1) ? (const float*)g_e0 : (const float*)g_e1;
    __shared__ float sa[16][128];
    int tid = threadIdx.x;
    int j = blockIdx.x * 128 + tid;
    int k0 = kbase + blockIdx.y * kslab;
    float acc[16];
#pragma unroll
    for (int bi = 0; bi < 16; bi++) acc[bi] = 0.f;
    for (int kt = k0; kt < k0 + kslab; kt += 128) {
#pragma unroll
        for (int i = 0; i < 16; i++) sa[i][tid] = A[i * K + kt + tid];
        __syncthreads();
#pragma unroll 8
        for (int kk = 0; kk < 128; kk++) {
            float wv = W[(size_t)(kt + kk) * Ncol + j];
#pragma unroll
            for (int bi = 0; bi < 16; bi++) acc[bi] += sa[bi][kk] * wv;
        }
        __syncthreads();
    }
#pragma unroll
    for (int bi = 0; bi < 16; bi++)
        g_part[((size_t)(part_base + blockIdx.y) * 16 + bi) * Ncol + j] = acc[bi];
}

__global__ void k_fcsum(int which, const float* __restrict__ bias,
                        int Ncol, int nsplit) {
    float* C = (which == 0) ? g_e0 : g_e1;
    int i = blockIdx.x * blockDim.x + threadIdx.x;
    if (i < 16 * Ncol) {
        float s = 0.f;
        for (int p = 0; p < nsplit; p++) s += g_part[(size_t)p * 16 * Ncol + i];
        C[i] = elu1(s + bias[i % Ncol]);
    }
}

// ---------------- tail ---------------------------------------------------------
__global__ void k_tail(const float* __restrict__ bias,
                       const float* __restrict__ lw, const float* __restrict__ lb,
                       float* __restrict__ out, int out_n) {
    __shared__ float se2[B_ * OMIC_];
    int t = threadIdx.x;
    for (int i = t; i < B_ * OMIC_; i += 1024) {
        float s = 0.f;
#pragma unroll
        for (int p = 0; p < 4; p++) s += g_part[p * (B_ * OMIC_) + i];
        se2[i] = elu1(s + bias[i & (OMIC_ - 1)]);
    }
    __syncthreads();
    if (t < 32 && t < out_n) {
        int bi = t >> 1, o = t & 1;
        float a = 0.f;
        for (int k = 0; k < OMIC_; k++) a += se2[bi * OMIC_ + k] * lw[k * 2 + o];
        out[t] = a + lb[o];
    }
}

// ---------------- driver --------------------------------------------------------
extern "C" void kernel_launch(void* const* d_in, const int* in_sizes, int n_in,
                              void* d_out, int out_size) {
    const float* x   = (const float*)d_in[0];
    const void*  ei  = d_in[1];
    const float* w1  = (const float*)d_in[2];
    const float* as1 = (const float*)d_in[3];
    const float* ad1 = (const float*)d_in[4];
    const float* b1  = (const float*)d_in[5];
    const float* p1w = (const float*)d_in[6];
    const float* p1b = (const float*)d_in[7];
    const float* w2  = (const float*)d_in[8];
    const float* as2 = (const float*)d_in[9];
    const float* ad2 = (const float*)d_in[10];
    const float* b2  = (const float*)d_in[11];
    const float* p2w = (const float*)d_in[12];
    const float* p2b = (const float*)d_in[13];
    const float* lnw = (const float*)d_in[14];
    const float* lnb = (const float*)d_in[15];
    const float* e0w = (const float*)d_in[16];
    const float* e0b = (const float*)d_in[17];
    const float* e1w = (const float*)d_in[18];
    const float* e1b = (const float*)d_in[19];
    const float* e2w = (const float*)d_in[20];
    const float* e2b = (const float*)d_in[21];
    const float* lw  = (const float*)d_in[22];
    const float* lb  = (const float*)d_in[23];
    float* out = (float*)d_out;

    cudaStream_t s2;
    cudaStreamCreateWithFlags(&s2, cudaStreamNonBlocking);
    cudaEvent_t eFork, eCsr, eAgg1, eSide;
    cudaEventCreateWithFlags(&eFork, cudaEventDisableTiming);
    cudaEventCreateWithFlags(&eCsr,  cudaEventDisableTiming);
    cudaEventCreateWithFlags(&eAgg1, cudaEventDisableTiming);
    cudaEventCreateWithFlags(&eSide, cudaEventDisableTiming);

    // ---- fork: side stream builds CSR while main does gemm1
    cudaEventRecord(eFork, 0);
    cudaStreamWaitEvent(s2, eFork, 0);

    k_zero<<<128, 256, 0, s2>>>(ei);
    k_deg<<<E_ / 256, 256, 0, s2>>>(ei);
    k_scan1<<<128, 256, 0, s2>>>();
    k_scan3b<<<128, 256, 0, s2>>>();
    k_scatter<<<E_ / 256, 256, 0, s2>>>(ei);
    k_sortseg<<<NT_ / 256, 256, 0, s2>>>();
    cudaEventRecord(eCsr, s2);
    k_x0<<<NT_ / 8, 256, 0, s2>>>(x);

    // ---- main: GAT layer 1 (attn fused in gemm)
    k_gemm_tc<<<dim3(NT_ / 128, 2), 256>>>(x, 0, w1, INCH_, as1, ad1);
    cudaStreamWaitEvent(0, eCsr, 0);
    k_agg<<<NT_ / 8, 256>>>(b1, p1w, p1b, 1, 1);
    cudaEventRecord(eAgg1, 0);

    // ---- side: LN(seg0,1) + fc0 k-parts 0-7
    cudaStreamWaitEvent(s2, eAgg1, 0);
    k_ln<<<32, 256, 0, s2>>>(lnw, lnb, 0);
    k_fc<<<dim3(FC0_ / 128, 8), 128, 0, s2>>>(0, e0w, 3 * N_, FC0_, 0, 0, 512);
    cudaEventRecord(eSide, s2);

    // ---- main: GAT layer 2
    k_gemm_tc<<<dim3(NT_ / 128, 2), 256>>>(nullptr, 1, w2, HC_, as2, ad2);
    k_agg<<<NT_ / 8, 256>>>(b2, p2w, p2b, 0, 2);
    k_ln<<<16, 256>>>(lnw, lnb, 1);
    k_fc<<<dim3(FC0_ / 128, 4), 128>>>(0, e0w, 3 * N_, FC0_, 4096, 8, 512);

    // ---- join + FC tail
    cudaStreamWaitEvent(0, eSide, 0);
    k_fcsum<<<(16 * FC0_ + 255) / 256, 256>>>(0, e0b, FC0_, 12);
    k_fc<<<dim3(FC1_ / 128, 4), 128>>>(1, e1w, FC0_, FC1_, 0, 0, 256);
    k_fcsum<<<(16 * FC1_ + 255) / 256, 256>>>(1, e1b, FC1_, 4);
    k_fc<<<dim3(OMIC_ / 128, 4), 128>>>(2, e2w, FC1_, OMIC_, 0, 0, 128);
    k_tail<<<1, 1024>>>(e2b, lw, lb, out, out_size);
}

// round 12
// speedup vs baseline: 1.0414x; 1.0414x over previous
#include <cuda_runtime.h>
#include <cuda_fp16.h>
#include <cuda_bf16.h>
#include <math.h>

#define NT_   32768
#define B_    16
#define N_    2048
#define INCH_ 128
#define H_    4
#define C_    64
#define HC_   256
#define E_    524288
#define FC0_  1024
#define FC1_  512
#define OMIC_ 128
#define OUT_  2

// ---------------- scratch (static device globals) --------------------------
__device__ __align__(16) float g_xw[NT_ * HC_];
__device__ __align__(16) __half g_xwh[NT_ * HC_];
__device__ __align__(16) float g_h [NT_ * HC_];
__device__ __align__(16) float g_asrc[NT_ * 4];
__device__ __align__(16) float g_adst[NT_ * 4];
__device__ int   g_deg[NT_];
__device__ int   g_cur[NT_];
__device__ int   g_row[NT_ + 1];
__device__ int   g_blk[128];
__device__ int   g_csr[E_];
__device__ __align__(16) float g_feat[B_ * 3 * N_];
__device__ __align__(16) float g_part[12 * B_ * FC0_];
__device__ int   g_i64;

__device__ __forceinline__ float elu1(float x)  { return x > 0.f ? x : (expf(x) - 1.f); }
__device__ __forceinline__ float lrelu(float x) { return x > 0.f ? x : 0.2f * x; }

__device__ __forceinline__ int ld_idx(const void* ei, int i) {
    if (g_i64) return (int)((const long long*)ei)[i];
    return ((const int*)ei)[i];
}

// ---------------- zero + detect + x0 (fused) ---------------------------------
__global__ void k_zero(const void* ei, const float* __restrict__ x) {
    int tid = blockIdx.x * blockDim.x + threadIdx.x;   // 4096*256 = 1M threads
    if (tid < NT_) { g_deg[tid] = 0; g_cur[tid] = 0; }
    if (blockIdx.x == 0 && threadIdx.x < 32) {
        const long long* p64 = (const long long*)ei;
        long long v = p64[threadIdx.x];
        unsigned bad = __ballot_sync(0xffffffffu, v < 0 || v >= NT_);
        if (threadIdx.x == 0) g_i64 = (bad == 0);
    }
    // x0: one warp per node
    int n = tid >> 5;
    int lane = threadIdx.x & 31;
    if (n < NT_) {
        float4 v = *(const float4*)(x + (size_t)n * INCH_ + lane * 4);
        float s = v.x + v.y + v.z + v.w;
#pragma unroll
        for (int off = 16; off >= 1; off >>= 1)
            s += __shfl_xor_sync(0xffffffffu, s, off);
        if (lane == 0)
            g_feat[(n >> 11) * (3 * N_) + (n & 2047)] = s * (1.f / 128.f);
    }
}

__global__ void k_deg(const void* __restrict__ ei) {
    int e = blockIdx.x * blockDim.x + threadIdx.x;
    if (e < E_) atomicAdd(&g_deg[ld_idx(ei, E_ + e) & (NT_ - 1)], 1);
}

__global__ void k_scan1() {
    __shared__ int wt[8];
    int t = threadIdx.x;
    int i = blockIdx.x * 256 + t;
    int v = g_deg[i];
    int lane = t & 31, w = t >> 5;
    int inc = v;
#pragma unroll
    for (int off = 1; off < 32; off <<= 1) {
        int u = __shfl_up_sync(0xffffffffu, inc, off);
        if (lane >= off) inc += u;
    }
    if (lane == 31) wt[w] = inc;
    __syncthreads();
    if (t == 0) {
        int run = 0;
#pragma unroll
        for (int k = 0; k < 8; k++) { int x = wt[k]; wt[k] = run; run += x; }
        g_blk[blockIdx.x] = run;
    }
    __syncthreads();
    g_row[i] = inc - v + wt[w];
}

__global__ void k_scan3b() {
    __shared__ int part[4];
    int t = threadIdx.x;
    int v = (t < 128 && t < blockIdx.x) ? g_blk[t] : 0;
    if (t < 128) {
        int u = v;
#pragma unroll
        for (int off = 16; off >= 1; off >>= 1)
            u += __shfl_xor_sync(0xffffffffu, u, off);
        if ((t & 31) == 0) part[t >> 5] = u;
    }
    __syncthreads();
    int pre = part[0] + part[1] + part[2] + part[3];
    g_row[blockIdx.x * 256 + t] += pre;
    if (blockIdx.x == 127 && t == 255) g_row[NT_] = pre + g_blk[127];
}

__global__ void k_scatter(const void* __restrict__ ei) {
    int e = blockIdx.x * blockDim.x + threadIdx.x;
    if (e < E_) {
        int d = ld_idx(ei, E_ + e) & (NT_ - 1);
        int s = ld_idx(ei, e) & (NT_ - 1);
        int pos = g_row[d] + atomicAdd(&g_cur[d], 1);
        g_csr[pos] = s;
    }
}

__global__ void k_sortseg() {
    int n = blockIdx.x * blockDim.x + threadIdx.x;
    if (n >= NT_) return;
    int r0 = g_row[n], r1 = g_row[n + 1];
    int len = r1 - r0;
    if (len <= 1) return;
    if (len <= 96) {
        int buf[96];
        for (int i = 0; i < len; i++) buf[i] = g_csr[r0 + i];
        for (int i = 1; i < len; i++) {
            int v = buf[i]; int j = i - 1;
            while (j >= 0 && buf[j] > v) { buf[j + 1] = buf[j]; j--; }
            buf[j + 1] = v;
        }
        for (int i = 0; i < len; i++) g_csr[r0 + i] = buf[i];
    } else {
        for (int i = r0 + 1; i < r1; i++) {
            int v = g_csr[i]; int j = i - 1;
            while (j >= r0 && g_csr[j] > v) { g_csr[j + 1] = g_csr[j]; j--; }
            g_csr[j + 1] = v;
        }
    }
}

// ---------------- bf16 3-pass tensor GEMM + fused attention dots -------------
__device__ __forceinline__ void mma16(float* c, const unsigned* a,
                                      unsigned b0, unsigned b1) {
    asm volatile(
        "mma.sync.aligned.m16n8k16.row.col.f32.bf16.bf16.f32 "
        "{%0,%1,%2,%3},{%4,%5,%6,%7},{%8,%9},{%0,%1,%2,%3};"
        : "+f"(c[0]), "+f"(c[1]), "+f"(c[2]), "+f"(c[3])
        : "r"(a[0]), "r"(a[1]), "r"(a[2]), "r"(a[3]), "r"(b0), "r"(b1));
}

__device__ __forceinline__ unsigned sptr(const void* p) {
    return (unsigned)__cvta_generic_to_shared(p);
}

__device__ __forceinline__ void ldsm4(unsigned* r, unsigned addr) {
    asm volatile("ldmatrix.sync.aligned.m8n8.x4.shared.b16 {%0,%1,%2,%3}, [%4];"
                 : "=r"(r[0]), "=r"(r[1]), "=r"(r[2]), "=r"(r[3]) : "r"(addr));
}

__device__ __forceinline__ void ldsm4t(unsigned* r, unsigned addr) {
    asm volatile("ldmatrix.sync.aligned.m8n8.x4.trans.shared.b16 {%0,%1,%2,%3}, [%4];"
                 : "=r"(r[0]), "=r"(r[1]), "=r"(r[2]), "=r"(r[3]) : "r"(addr));
}

__global__ __launch_bounds__(256, 2)
void k_gemm_tc(const float* __restrict__ Aext, int useH,
               const float* __restrict__ W, int K,
               const float* __restrict__ att_s, const float* __restrict__ att_d) {
    const float* A = useH ? (const float*)g_h : Aext;
    __shared__ __nv_bfloat16 AsH[128][40];
    __shared__ __nv_bfloat16 AsL[128][40];
    __shared__ __nv_bfloat16 BsH[32][136];
    __shared__ __nv_bfloat16 BsL[32][136];
    int tid = threadIdx.x;
    int lid = tid & 31, wid = tid >> 5;
    int wr = wid >> 1, wc = wid & 1;
    int lrow = lid & 7, seg = lid >> 3;

    const float* Ab = A + (size_t)blockIdx.x * 128 * K;
    const float* Wb = W + blockIdx.y * 128;

    float c[2][8][4];
#pragma unroll
    for (int mt = 0; mt < 2; mt++)
#pragma unroll
        for (int nt = 0; nt < 8; nt++)
#pragma unroll
            for (int q = 0; q < 4; q++) c[mt][nt][q] = 0.f;

    for (int k0 = 0; k0 < K; k0 += 32) {
#pragma unroll
        for (int i = 0; i < 4; i++) {
            int id = tid + 256 * i;
            int row = id >> 3, kq = id & 7;
            float4 v = *(const float4*)(Ab + (size_t)row * K + k0 + kq * 4);
            __nv_bfloat162 h01 = __floats2bfloat162_rn(v.x, v.y);
            __nv_bfloat162 h23 = __floats2bfloat162_rn(v.z, v.w);
            __nv_bfloat162 l01 = __floats2bfloat162_rn(v.x - __bfloat162float(h01.x),
                                                       v.y - __bfloat162float(h01.y));
            __nv_bfloat162 l23 = __floats2bfloat162_rn(v.z - __bfloat162float(h23.x),
                                                       v.w - __bfloat162float(h23.y));
            *(__nv_bfloat162*)&AsH[row][kq * 4]     = h01;
            *(__nv_bfloat162*)&AsH[row][kq * 4 + 2] = h23;
            *(__nv_bfloat162*)&AsL[row][kq * 4]     = l01;
            *(__nv_bfloat162*)&AsL[row][kq * 4 + 2] = l23;
        }
#pragma unroll
        for (int i = 0; i < 4; i++) {
            int id = tid + 256 * i;
            int kr = id >> 5, nq = id & 31;
            float4 v = *(const float4*)(Wb + (size_t)(k0 + kr) * HC_ + nq * 4);
            __nv_bfloat162 h01 = __floats2bfloat162_rn(v.x, v.y);
            __nv_bfloat162 h23 = __floats2bfloat162_rn(v.z, v.w);
            __nv_bfloat162 l01 = __floats2bfloat162_rn(v.x - __bfloat162float(h01.x),
                                                       v.y - __bfloat162float(h01.y));
            __nv_bfloat162 l23 = __floats2bfloat162_rn(v.z - __bfloat162float(h23.x),
                                                       v.w - __bfloat162float(h23.y));
            *(__nv_bfloat162*)&BsH[kr][nq * 4]     = h01;
            *(__nv_bfloat162*)&BsH[kr][nq * 4 + 2] = h23;
            *(__nv_bfloat162*)&BsL[kr][nq * 4]     = l01;
            *(__nv_bfloat162*)&BsL[kr][nq * 4 + 2] = l23;
        }
        __syncthreads();

#pragma unroll
        for (int ks = 0; ks < 2; ks++) {
            int kc = ks * 16;
            unsigned aH[2][4], aL[2][4];
            int ar = (seg & 1) * 8 + lrow;
            int ac = kc + (seg >> 1) * 8;
#pragma unroll
            for (int mt = 0; mt < 2; mt++) {
                int m = wr * 32 + mt * 16 + ar;
                ldsm4(aH[mt], sptr(&AsH[m][ac]));
                ldsm4(aL[mt], sptr(&AsL[m][ac]));
            }
            int br = kc + (seg & 1) * 8 + lrow;
            int bcoff = (seg >> 1) * 8;
#pragma unroll
            for (int ntp = 0; ntp < 4; ntp++) {
                int n0 = wc * 64 + ntp * 16 + bcoff;
                unsigned bH[4], bL[4];
                ldsm4t(bH, sptr(&BsH[br][n0]));
                ldsm4t(bL, sptr(&BsL[br][n0]));
#pragma unroll
                for (int half = 0; half < 2; half++) {
                    int nt = 2 * ntp + half;
                    unsigned b0H = bH[2 * half], b1H = bH[2 * half + 1];
                    unsigned b0L = bL[2 * half], b1L = bL[2 * half + 1];
#pragma unroll
                    for (int mt = 0; mt < 2; mt++) {
                        mma16(c[mt][nt], aH[mt], b0H, b1H);
                        mma16(c[mt][nt], aL[mt], b0H, b1H);
                        mma16(c[mt][nt], aH[mt], b0L, b1L);
                    }
                }
            }
        }
        __syncthreads();
    }

    int g4 = lid >> 2, t4 = lid & 3;

#pragma unroll
    for (int mt = 0; mt < 2; mt++) {
#pragma unroll
        for (int nt = 0; nt < 8; nt++) {
            int row = blockIdx.x * 128 + wr * 32 + mt * 16 + g4;
            int col = blockIdx.y * 128 + wc * 64 + nt * 8 + 2 * t4;
            float2 v0 = {c[mt][nt][0], c[mt][nt][1]};
            float2 v1 = {c[mt][nt][2], c[mt][nt][3]};
            *(float2*)(g_xw + (size_t)row * HC_ + col)       = v0;
            *(float2*)(g_xw + (size_t)(row + 8) * HC_ + col) = v1;
            *(__half2*)(g_xwh + (size_t)row * HC_ + col)       = __floats2half2_rn(v0.x, v0.y);
            *(__half2*)(g_xwh + (size_t)(row + 8) * HC_ + col) = __floats2half2_rn(v1.x, v1.y);
        }
    }

    // fused attention dots: this warp's 64 cols == one head
    int head = blockIdx.y * 2 + wc;
    const float* Asv = att_s + head * 64;
    const float* Adv = att_d + head * 64;
#pragma unroll
    for (int mt = 0; mt < 2; mt++) {
        float s0 = 0.f, s1 = 0.f, d0 = 0.f, d1 = 0.f;
#pragma unroll
        for (int nt = 0; nt < 8; nt++) {
            int cb = nt * 8 + 2 * t4;
            float a0 = Asv[cb], a1 = Asv[cb + 1];
            float b0 = Adv[cb], b1 = Adv[cb + 1];
            s0 += c[mt][nt][0] * a0 + c[mt][nt][1] * a1;
            s1 += c[mt][nt][2] * a0 + c[mt][nt][3] * a1;
            d0 += c[mt][nt][0] * b0 + c[mt][nt][1] * b1;
            d1 += c[mt][nt][2] * b0 + c[mt][nt][3] * b1;
        }
#pragma unroll
        for (int off = 1; off <= 2; off <<= 1) {
            s0 += __shfl_xor_sync(0xffffffffu, s0, off);
            s1 += __shfl_xor_sync(0xffffffffu, s1, off);
            d0 += __shfl_xor_sync(0xffffffffu, d0, off);
            d1 += __shfl_xor_sync(0xffffffffu, d1, off);
        }
        if (t4 == 0) {
            int r = blockIdx.x * 128 + wr * 32 + mt * 16 + g4;
            g_asrc[r * 4 + head]       = s0;
            g_adst[r * 4 + head]       = d0;
            g_asrc[(r + 8) * 4 + head] = s1;
            g_adst[(r + 8) * 4 + head] = d1;
        }
    }
}

// ---------------- GAT aggregation (warp per node, fp16 gather) ----------------
__global__ void k_agg(const float* __restrict__ bias,
                      const float* __restrict__ poolw,
                      const float* __restrict__ poolb,
                      int writeH, int seg) {
    int n = (blockIdx.x * blockDim.x + threadIdx.x) >> 5;
    int lane = threadIdx.x & 31;
    if (n >= NT_) return;
    int h = lane >> 3;

    float4 d4 = *(const float4*)(g_adst + n * 4);
    float4 s4 = *(const float4*)(g_asrc + n * 4);
    float adh = (h == 0) ? d4.x : (h == 1) ? d4.y : (h == 2) ? d4.z : d4.w;
    float ash = (h == 0) ? s4.x : (h == 1) ? s4.y : (h == 2) ? s4.z : s4.w;

    int r0 = g_row[n], r1 = g_row[n + 1];

    float wself = __expf(lrelu(ash + adh));
    float den = wself;
    const float4* xp = (const float4*)(g_xw + (size_t)n * HC_ + lane * 8);
    float4 q0 = xp[0], q1 = xp[1];
    float4 acc0 = {wself*q0.x, wself*q0.y, wself*q0.z, wself*q0.w};
    float4 acc1 = {wself*q1.x, wself*q1.y, wself*q1.z, wself*q1.w};

    int sN = 0; float asN = 0.f;
    if (r0 < r1) { sN = g_csr[r0]; asN = g_asrc[sN * 4 + h]; }
    for (int e = r0; e < r1; e++) {
        int s = sN; float as = asN;
        int eN = (e + 1 < r1) ? e + 1 : e;
        sN = g_csr[eN];
        asN = g_asrc[sN * 4 + h];
        float wgt = __expf(lrelu(as + adh));
        den += wgt;
        uint4 q = *(const uint4*)(g_xwh + (size_t)s * HC_ + lane * 8);
        float2 f0 = __half22float2(*(__half2*)&q.x);
        float2 f1 = __half22float2(*(__half2*)&q.y);
        float2 f2 = __half22float2(*(__half2*)&q.z);
        float2 f3 = __half22float2(*(__half2*)&q.w);
        acc0.x += wgt * f0.x; acc0.y += wgt * f0.y;
        acc0.z += wgt * f1.x; acc0.w += wgt * f1.y;
        acc1.x += wgt * f2.x; acc1.y += wgt * f2.y;
        acc1.z += wgt * f3.x; acc1.w += wgt * f3.y;
    }
    float rden = 1.f / (den + 1e-16f);
    acc0.x *= rden; acc0.y *= rden; acc0.z *= rden; acc0.w *= rden;
    acc1.x *= rden; acc1.y *= rden; acc1.z *= rden; acc1.w *= rden;

    const float* bp = bias + lane * 8;
    float v[8];
    v[0] = elu1(acc0.x + bp[0]); v[1] = elu1(acc0.y + bp[1]);
    v[2] = elu1(acc0.z + bp[2]); v[3] = elu1(acc0.w + bp[3]);
    v[4] = elu1(acc1.x + bp[4]); v[5] = elu1(acc1.y + bp[5]);
    v[6] = elu1(acc1.z + bp[6]); v[7] = elu1(acc1.w + bp[7]);

    if (writeH) {
        float4 o0 = {v[0], v[1], v[2], v[3]};
        float4 o1 = {v[4], v[5], v[6], v[7]};
        *(float4*)(g_h + (size_t)n * HC_ + lane * 8)     = o0;
        *(float4*)(g_h + (size_t)n * HC_ + lane * 8 + 4) = o1;
    }

    const float* pw = poolw + lane * 8;
    float p = v[0]*pw[0] + v[1]*pw[1] + v[2]*pw[2] + v[3]*pw[3]
            + v[4]*pw[4] + v[5]*pw[5] + v[6]*pw[6] + v[7]*pw[7];
#pragma unroll
    for (int off = 16; off >= 1; off >>= 1)
        p += __shfl_xor_sync(0xffffffffu, p, off);
    if (lane == 0)
        g_feat[(n >> 11) * (3 * N_) + seg * N_ + (n & 2047)] = p + poolb[0];
}

// ---------------- LayerNorm in place (48 rows) --------------------------------
__global__ void k_ln(const float* __restrict__ w, const float* __restrict__ b) {
    __shared__ float red[8];
    __shared__ float tot;
    int row = blockIdx.x;
    float* p = g_feat + (row / 3) * (3 * N_) + (row % 3) * N_;
    int t = threadIdx.x;
    float v[8];
    float s = 0.f;
#pragma unroll
    for (int i = 0; i < 8; i++) { v[i] = p[t + 256 * i]; s += v[i]; }
#pragma unroll
    for (int off = 16; off >= 1; off >>= 1) s += __shfl_xor_sync(0xffffffffu, s, off);
    if ((t & 31) == 0) red[t >> 5] = s;
    __syncthreads();
    if (t == 0) { float z = 0.f; for (int i = 0; i < 8; i++) z += red[i]; tot = z; }
    __syncthreads();
    float mu = tot * (1.f / 2048.f);
    float q = 0.f;
#pragma unroll
    for (int i = 0; i < 8; i++) { float d = v[i] - mu; q += d * d; }
#pragma unroll
    for (int off = 16; off >= 1; off >>= 1) q += __shfl_xor_sync(0xffffffffu, q, off);
    __syncthreads();
    if ((t & 31) == 0) red[t >> 5] = q;
    __syncthreads();
    if (t == 0) { float z = 0.f; for (int i = 0; i < 8; i++) z += red[i]; tot = z; }
    __syncthreads();
    float r = rsqrtf(tot * (1.f / 2048.f) + 1e-5f);
#pragma unroll
    for (int i = 0; i < 8; i++) {
        int idx = t + 256 * i;
        p[idx] = (v[i] - mu) * r * w[idx] + b[idx];
    }
}

// ---------------- fc0 partial GEMM (12 k-splits) ------------------------------
__global__ void k_fc0(const float* __restrict__ W) {
    __shared__ float sa[16][128];
    int tid = threadIdx.x;
    int j = blockIdx.x * 128 + tid;
    int k0 = blockIdx.y * 512;
    float acc[16];
#pragma unroll
    for (int bi = 0; bi < 16; bi++) acc[bi] = 0.f;
    for (int kt = k0; kt < k0 + 512; kt += 128) {
#pragma unroll
        for (int i = 0; i < 16; i++) sa[i][tid] = g_feat[i * (3 * N_) + kt + tid];
        __syncthreads();
#pragma unroll 8
        for (int kk = 0; kk < 128; kk++) {
            float wv = W[(size_t)(kt + kk) * FC0_ + j];
#pragma unroll
            for (int bi = 0; bi < 16; bi++) acc[bi] += sa[bi][kk] * wv;
        }
        __syncthreads();
    }
#pragma unroll
    for (int bi = 0; bi < 16; bi++)
        g_part[((size_t)blockIdx.y * 16 + bi) * FC0_ + j] = acc[bi];
}

// ---------------- fused FC tail: fcsum0 + fc1 + fc2 + last --------------------
__global__ __launch_bounds__(512)
void k_fctail(const float* __restrict__ e0b,
              const float* __restrict__ e1w, const float* __restrict__ e1b,
              const float* __restrict__ e2w, const float* __restrict__ e2b,
              const float* __restrict__ lw,  const float* __restrict__ lb,
              float* __restrict__ out, int out_n) {
    __shared__ float se0[FC0_];
    __shared__ float se1[FC1_];
    __shared__ float se2[OMIC_];
    int b = blockIdx.x;            // batch row
    int t = threadIdx.x;           // 512

    // e0 = elu(sum of 12 partials + bias)
    for (int j = t; j < FC0_; j += 512) {
        float s = 0.f;
#pragma unroll
        for (int p = 0; p < 12; p++)
            s += g_part[((size_t)p * 16 + b) * FC0_ + j];
        se0[j] = elu1(s + e0b[j]);
    }
    __syncthreads();

    // e1 = elu(e0 @ W1 + b1)    [1024 x 512]
    {
        float s = 0.f;
        for (int k = 0; k < FC0_; k++)
            s += se0[k] * e1w[(size_t)k * FC1_ + t];
        se1[t] = elu1(s + e1b[t]);
    }
    __syncthreads();

    // e2 = elu(e1 @ W2 + b2)    [512 x 128]
    if (t < OMIC_) {
        float s = 0.f;
        for (int k = 0; k < FC1_; k++)
            s += se1[k] * e2w[(size_t)k * OMIC_ + t];
        se2[t] = elu1(s + e2b[t]);
    }
    __syncthreads();

    // out = e2 @ lw + lb        [128 x 2]
    if (t < OUT_) {
        float a = 0.f;
        for (int k = 0; k < OMIC_; k++) a += se2[k] * lw[k * OUT_ + t];
        int oi = b * OUT_ + t;
        if (oi < out_n) out[oi] = a + lb[t];
    }
}

// ---------------- driver --------------------------------------------------------
extern "C" void kernel_launch(void* const* d_in, const int* in_sizes, int n_in,
                              void* d_out, int out_size) {
    const float* x   = (const float*)d_in[0];
    const void*  ei  = d_in[1];
    const float* w1  = (const float*)d_in[2];
    const float* as1 = (const float*)d_in[3];
    const float* ad1 = (const float*)d_in[4];
    const float* b1  = (const float*)d_in[5];
    const float* p1w = (const float*)d_in[6];
    const float* p1b = (const float*)d_in[7];
    const float* w2  = (const float*)d_in[8];
    const float* as2 = (const float*)d_in[9];
    const float* ad2 = (const float*)d_in[10];
    const float* b2  = (const float*)d_in[11];
    const float* p2w = (const float*)d_in[12];
    const float* p2b = (const float*)d_in[13];
    const float* lnw = (const float*)d_in[14];
    const float* lnb = (const float*)d_in[15];
    const float* e0w = (const float*)d_in[16];
    const float* e0b = (const float*)d_in[17];
    const float* e1w = (const float*)d_in[18];
    const float* e1b = (const float*)d_in[19];
    const float* e2w = (const float*)d_in[20];
    const float* e2b = (const float*)d_in[21];
    const float* lw  = (const float*)d_in[22];
    const float* lb  = (const float*)d_in[23];
    float* out = (float*)d_out;

    k_zero<<<4096, 256>>>(ei, x);                                   // 1 (zero+detect+x0)
    k_deg<<<E_ / 256, 256>>>(ei);                                   // 2
    k_scan1<<<128, 256>>>();                                        // 3
    k_gemm_tc<<<dim3(NT_ / 128, 2), 256>>>(x, 0, w1, INCH_, as1, ad1); // 4 <- profiled
    k_scan3b<<<128, 256>>>();                                       // 5
    k_scatter<<<E_ / 256, 256>>>(ei);                               // 6
    k_sortseg<<<NT_ / 256, 256>>>();                                // 7
    k_agg<<<NT_ / 8, 256>>>(b1, p1w, p1b, 1, 1);                    // 8
    k_gemm_tc<<<dim3(NT_ / 128, 2), 256>>>(nullptr, 1, w2, HC_, as2, ad2); // 9
    k_agg<<<NT_ / 8, 256>>>(b2, p2w, p2b, 0, 2);                    // 10
    k_ln<<<48, 256>>>(lnw, lnb);                                    // 11
    k_fc0<<<dim3(FC0_ / 128, 12), 128>>>(e0w);                      // 12
    k_fctail<<<B_, 512>>>(e0b, e1w, e1b, e2w, e2b, lw, lb, out, out_size); // 13
}